// round 7
// baseline (speedup 1.0000x reference)
#include <cuda_runtime.h>
#include <math.h>

// Problem constants
#define T_LEN 1200
#define BATCH 32
#define IDIM  512
#define HDIM  512
#define G4    2048            // 4*H
#define XPN   78643200        // T*B*4H
#define NCTA  128             // persistent recurrence grid
#define NTHR  256

typedef unsigned long long u64;

// Packed fp32x2 FMA (kept in GEMM; throughput-neutral but halves issue slots)
__device__ __forceinline__ void fma2(u64& d, u64 a, u64 b) {
    asm("fma.rn.f32x2 %0, %1, %2, %0;" : "+l"(d) : "l"(a), "l"(b));
}
__device__ __forceinline__ float2 unp2(u64 v) {
    float2 r; asm("mov.b64 {%0, %1}, %2;" : "=f"(r.x), "=f"(r.y) : "l"(v));
    return r;
}
__device__ __forceinline__ u64 dup2(float v) {
    u64 r; asm("mov.b64 %0, {%1, %1};" : "=l"(r) : "f"(v));
    return r;
}

// Scratch (device globals — no runtime allocation allowed)
// x_proj layout: [dir][ (t*2048 + g*512 + j) * 32 + b ]   (batch-minor)
__device__ float g_xp[2][XPN];
__device__ float g_h[2][2][BATCH * HDIM];   // [parity][dir][b*512 + j]
__device__ unsigned g_arrive;               // grid-barrier counter

// ---------------------------------------------------------------------------
__global__ void zero_out_kernel(float4* __restrict__ o) {
    const int n4 = (T_LEN * BATCH * HDIM) / 4;
    for (int i = blockIdx.x * blockDim.x + threadIdx.x; i < n4;
         i += gridDim.x * blockDim.x)
        o[i] = make_float4(0.f, 0.f, 0.f, 0.f);
}

__global__ void zero_state_kernel() {
    int i = blockIdx.x * blockDim.x + threadIdx.x;  // 65536 threads
    if (i < 2 * 2 * BATCH * HDIM)
        (&g_h[0][0][0])[i] = 0.f;
    if (i == 0) g_arrive = 0u;
}

// ---------------------------------------------------------------------------
// Input projection GEMM (unchanged): M=38400, N=2048, K=512.
// Output b-minor: xp[(t*2048 + n)*32 + b].
// ---------------------------------------------------------------------------
__global__ __launch_bounds__(256, 2)
void xproj_gemm(const float* __restrict__ x, const int* __restrict__ lens,
                const float* __restrict__ w, const float* __restrict__ b1,
                const float* __restrict__ b2, int rev)
{
    __shared__ float as[2][8][132];
    __shared__ float bs[2][8][132];
    float* __restrict__ out = g_xp[rev];

    const int tid = threadIdx.x;
    const int m0 = blockIdx.x * 128;
    const int n0 = blockIdx.y * 128;

    const int lr = tid >> 1;
    const int lk = (tid & 1) * 4;

    const int m = m0 + lr;
    const float* arow;
    if (!rev) {
        arow = x + (size_t)m * IDIM;
    } else {
        int t = m >> 5, b = m & 31;
        int st = lens[b] - 1 - t;
        if (st < 0) st = 0;
        arow = x + ((size_t)st * BATCH + b) * IDIM;
    }
    const float* brow = w + (size_t)(n0 + lr) * IDIM;

    float4 areg = *(const float4*)(arow + lk);
    float4 breg = *(const float4*)(brow + lk);

    u64 acc2[8][4];
#pragma unroll
    for (int i = 0; i < 8; i++)
#pragma unroll
        for (int p = 0; p < 4; p++) acc2[i][p] = 0ULL;

    const int wid = tid >> 5, lane = tid & 31;
    const int wm = (wid >> 1) * 32, wn = (wid & 1) * 64;
    const int lm = (lane & 3) * 4,  ln = (lane >> 2) * 4;

    as[0][lk + 0][lr] = areg.x; as[0][lk + 1][lr] = areg.y;
    as[0][lk + 2][lr] = areg.z; as[0][lk + 3][lr] = areg.w;
    bs[0][lk + 0][lr] = breg.x; bs[0][lk + 1][lr] = breg.y;
    bs[0][lk + 2][lr] = breg.z; bs[0][lk + 3][lr] = breg.w;
    __syncthreads();

    int buf = 0;
    for (int k0 = 8; k0 <= IDIM; k0 += 8) {
        const bool more = (k0 < IDIM);
        if (more) {
            areg = *(const float4*)(arow + k0 + lk);
            breg = *(const float4*)(brow + k0 + lk);
        }
#pragma unroll
        for (int kk = 0; kk < 8; kk++) {
            float4 a0  = *(const float4*)&as[buf][kk][wm + lm];
            float4 a1  = *(const float4*)&as[buf][kk][wm + lm + 16];
            ulonglong2 bq0 = *(const ulonglong2*)&bs[buf][kk][wn + ln];
            ulonglong2 bq1 = *(const ulonglong2*)&bs[buf][kk][wn + ln + 32];
            u64 b2v[4] = {bq0.x, bq0.y, bq1.x, bq1.y};
            float av[8] = {a0.x, a0.y, a0.z, a0.w, a1.x, a1.y, a1.z, a1.w};
#pragma unroll
            for (int i = 0; i < 8; i++) {
                u64 a2 = dup2(av[i]);
#pragma unroll
                for (int p = 0; p < 4; p++)
                    fma2(acc2[i][p], a2, b2v[p]);
            }
        }
        if (more) {
            buf ^= 1;
            as[buf][lk + 0][lr] = areg.x; as[buf][lk + 1][lr] = areg.y;
            as[buf][lk + 2][lr] = areg.z; as[buf][lk + 3][lr] = areg.w;
            bs[buf][lk + 0][lr] = breg.x; bs[buf][lk + 1][lr] = breg.y;
            bs[buf][lk + 2][lr] = breg.z; bs[buf][lk + 3][lr] = breg.w;
            __syncthreads();
        }
    }

    const int c0 = n0 + wn + ln;
    float bias[8];
#pragma unroll
    for (int p = 0; p < 4; p++) {
        int cc = c0 + (p & 1) * 2 + (p >> 1) * 32;
        bias[p * 2 + 0] = b1[cc + 0] + b2[cc + 0];
        bias[p * 2 + 1] = b1[cc + 1] + b2[cc + 1];
    }
#pragma unroll
    for (int i = 0; i < 8; i++) {
        int r = m0 + wm + lm + (i & 3) + ((i >= 4) ? 16 : 0);
        int t_ = r >> 5, b_ = r & 31;
        size_t base = ((size_t)t_ * G4) * 32 + b_;
#pragma unroll
        for (int p = 0; p < 4; p++) {
            int cc = c0 + (p & 1) * 2 + (p >> 1) * 32;
            float2 v = unp2(acc2[i][p]);
            out[base + (size_t)(cc + 0) * 32] = v.x + bias[p * 2 + 0];
            out[base + (size_t)(cc + 1) * 32] = v.y + bias[p * 2 + 1];
        }
    }
}

// ---------------------------------------------------------------------------
// Persistent recurrence, BOTH dirs per CTA: 128 CTAs x 256 threads.
// CTA owns j-columns [bid*4, bid*4+4) of both directions (16 gate-rows/dir).
// Intra-CTA K split across 8 warps; ONE grid barrier per step.
// SMEM: ws 64KB (W both dirs) + hs 128KB (h both dirs) + red 32KB = 224KB.
// ---------------------------------------------------------------------------
#define SMEM_FLOATS (16384 + 32768 + 8192)
#define SMEM_BYTES  (SMEM_FLOATS * 4)          // 229,376 <= 227KB optin

// word index of float4 chunk c (0..127) in row r/b, XOR-swizzled
#define WSW(r, c) (((r) << 9) + ((((c) ^ (((r) >> 1) & 7)) << 2)))
#define HSW(b, c) (((b) << 9) + ((((c) ^ (((b) >> 3) & 3)) << 2)))

__global__ __launch_bounds__(NTHR)
void lstm_persist(const float* __restrict__ whh_f,
                  const float* __restrict__ whh_b,
                  const int* __restrict__ lens, float* __restrict__ out)
{
    extern __shared__ float sm[];
    float* ws  = sm;                  // [32 rows][512]; row r = d*16+g*4+jl
    float* hs  = sm + 16384;          // [2 dir][32 b][512]
    float* red = sm + 49152;          // [2 dir][8 ks][16 r][32 b]

    const int bid = blockIdx.x;
    const int j0  = bid << 2;         // 4 j per CTA per dir
    const int tid = threadIdx.x;
    const int ks  = tid >> 5;         // warp = k-slice (64 k)
    const int ln  = tid & 31;

    // ---- load W_hh slices for both dirs (once, swizzled) ----
    // ws row r: d=r>>4, g=(r>>2)&3, jl=r&3  ->  W_d row g*512 + j0 + jl
#pragma unroll
    for (int it = 0; it < 16; it++) {
        int cid = it * 256 + tid;          // 0..4095 float4 chunks
        int r = cid >> 7, c = cid & 127;
        int d = r >> 4, g = (r >> 2) & 3, jl = r & 3;
        const float* __restrict__ wsrc = d ? whh_b : whh_f;
        float4 v = *(const float4*)(wsrc +
            (size_t)(g * HDIM + j0 + jl) * HDIM + (c << 2));
        *(float4*)&ws[WSW(r, c)] = v;
    }

    // compute identity: lane = rg*4 + bg
    const int rg = ln >> 2;           // 0..7 : rows 2rg, 2rg+1 (of 16)
    const int bg = ln & 3;            // 0..3 : b = bg*8 .. +7

    // cell identity: one cell per thread (2 dir x 4 j x 32 b)
    const int d_c = tid >> 7;
    const int j_c = (tid >> 5) & 3;
    const int b_c = tid & 31;
    const int jg  = j0 + j_c;
    const int len_c = lens[b_c];

    float c_reg = 0.f, h_reg = 0.f;

    // h copy identity
    const int l16 = ln >> 4;          // 0..1
    const int l15 = ln & 15;          // 0..15

    __syncthreads();  // ws ready

    // ---- initial h load (parity 0, both dirs; h = 0) ----
#pragma unroll
    for (int d = 0; d < 2; d++) {
        const float* __restrict__ hin = g_h[0][d];
#pragma unroll
        for (int i = 0; i < 16; i++) {
            int b = i * 2 + l16;
            int c = (ks << 4) + l15;
            float4 v = __ldcg((const float4*)(hin + (b << 9) + (c << 2)));
            *(float4*)&hs[(d << 14) + HSW(b, c)] = v;
        }
    }
    __syncwarp();

    for (int t = 0; t < T_LEN; t++) {
        // Prefetch xp for this thread's cell (b-minor -> coalesced)
        const float* xb = g_xp[d_c] + ((size_t)t * G4 + jg) * 32 + b_c;
        float xg0 = __ldg(xb + (size_t)0 * 512 * 32);
        float xg1 = __ldg(xb + (size_t)1 * 512 * 32);
        float xg2 = __ldg(xb + (size_t)2 * 512 * 32);
        float xg3 = __ldg(xb + (size_t)3 * 512 * 32);

        // ---- compute both dirs: partial gates over this warp's k-slice ----
        const int c0 = ks << 4;
#pragma unroll
        for (int d = 0; d < 2; d++) {
            const float* hsd = hs + (d << 14);
            float acc[2][8];
#pragma unroll
            for (int rr = 0; rr < 2; rr++)
#pragma unroll
                for (int i = 0; i < 8; i++) acc[rr][i] = 0.f;

#pragma unroll 2
            for (int c = c0; c < c0 + 16; c++) {
                float4 hv[8];
                const int hsw = ((c ^ bg) << 2);
#pragma unroll
                for (int i = 0; i < 8; i++)
                    hv[i] = *(const float4*)&hsd[(((bg << 3) + i) << 9) + hsw];
                float4 wv[2];
#pragma unroll
                for (int rr = 0; rr < 2; rr++) {
                    const int r = (d << 4) + (rg << 1) + rr;
                    wv[rr] = *(const float4*)&ws[(r << 9) + (((c ^ rg) << 2))];
                }
#pragma unroll
                for (int rr = 0; rr < 2; rr++)
#pragma unroll
                    for (int i = 0; i < 8; i++)
                        acc[rr][i] += wv[rr].x * hv[i].x + wv[rr].y * hv[i].y +
                                      wv[rr].z * hv[i].z + wv[rr].w * hv[i].w;
            }

            // store partials: red[d][ks][r][b]
#pragma unroll
            for (int rr = 0; rr < 2; rr++) {
                int r = (rg << 1) + rr;
                float* dst = red + (((d << 3) + ks) << 9) + (r << 5) + (bg << 3);
                *(float4*)(dst + 0) = make_float4(acc[rr][0], acc[rr][1],
                                                  acc[rr][2], acc[rr][3]);
                *(float4*)(dst + 4) = make_float4(acc[rr][4], acc[rr][5],
                                                  acc[rr][6], acc[rr][7]);
            }
        }
        __syncthreads();

        // ---- reduce 8 k-slices + LSTM cell (1 cell per thread) ----
        float s0 = xg0, s1 = xg1, s2 = xg2, s3 = xg3;
#pragma unroll
        for (int q = 0; q < 8; q++) {
            const float* pq =
                red + (((d_c << 3) + q) << 9) + b_c;
            s0 += pq[((0 * 4 + j_c) << 5)];
            s1 += pq[((1 * 4 + j_c) << 5)];
            s2 += pq[((2 * 4 + j_c) << 5)];
            s3 += pq[((3 * 4 + j_c) << 5)];
        }

        if (t < len_c) {
            float gi = 1.f / (1.f + __expf(-s0));
            float gf = 1.f / (1.f + __expf(-s1));
            float gg = tanhf(s2);
            float go = 1.f / (1.f + __expf(-s3));
            c_reg = gf * c_reg + gi * gg;
            h_reg = go * tanhf(c_reg);
            const int to = d_c ? (len_c - 1 - t) : t;
            atomicAdd(out + ((size_t)to * BATCH + b_c) * HDIM + jg, h_reg);
        }
        // always publish h (frozen past length) to the other parity
        __stcg(g_h[(t + 1) & 1][d_c] + (b_c << 9) + jg, h_reg);

        // ---- single grid barrier per step ----
        __threadfence();
        __syncthreads();
        if (tid == 0) {
            atomicAdd(&g_arrive, 1u);
            const unsigned tgt = (unsigned)(t + 1) * NCTA;
            while (*(volatile unsigned*)&g_arrive < tgt) { }
            __threadfence();
        }
        __syncthreads();

        // ---- load next h (both dirs, per-warp k-slice) ----
        const int par = (t + 1) & 1;
#pragma unroll
        for (int d = 0; d < 2; d++) {
            const float* __restrict__ hin = g_h[par][d];
#pragma unroll
            for (int i = 0; i < 16; i++) {
                int b = i * 2 + l16;
                int c = (ks << 4) + l15;
                float4 v = __ldcg((const float4*)(hin + (b << 9) + (c << 2)));
                *(float4*)&hs[(d << 14) + HSW(b, c)] = v;
            }
        }
        __syncwarp();
    }

    // Final states: h_n (2,B,H) then c_n (2,B,H)
    const size_t base = (size_t)T_LEN * BATCH * HDIM;
    out[base + d_c * BATCH * HDIM + (b_c << 9) + jg] = h_reg;
    out[base + 2 * BATCH * HDIM + d_c * BATCH * HDIM + (b_c << 9) + jg] = c_reg;
}

// ---------------------------------------------------------------------------
extern "C" void kernel_launch(void* const* d_in, const int* in_sizes, int n_in,
                              void* d_out, int out_size) {
    (void)in_sizes; (void)n_in; (void)out_size;
    const float* x      = (const float*)d_in[0];
    const int*   lens   = (const int*)d_in[1];
    const float* w_ih_f = (const float*)d_in[2];
    const float* w_hh_f = (const float*)d_in[3];
    const float* b_ih_f = (const float*)d_in[4];
    const float* b_hh_f = (const float*)d_in[5];
    const float* w_ih_b = (const float*)d_in[6];
    const float* w_hh_b = (const float*)d_in[7];
    const float* b_ih_b = (const float*)d_in[8];
    const float* b_hh_b = (const float*)d_in[9];
    float* out = (float*)d_out;

    cudaFuncSetAttribute(lstm_persist,
                         cudaFuncAttributeMaxDynamicSharedMemorySize, SMEM_BYTES);

    zero_out_kernel<<<2048, 256>>>((float4*)out);
    zero_state_kernel<<<256, 256>>>();

    dim3 gg(300, 16);  // M/128 x N/128
    xproj_gemm<<<gg, 256>>>(x, lens, w_ih_f, b_ih_f, b_hh_f, 0);
    xproj_gemm<<<gg, 256>>>(x, lens, w_ih_b, b_ih_b, b_hh_b, 1);

    lstm_persist<<<NCTA, NTHR, SMEM_BYTES>>>(w_hh_f, w_hh_b, lens, out);
}

// round 15
// speedup vs baseline: 1.0164x; 1.0164x over previous
#include <cuda_runtime.h>
#include <stdint.h>
#include <math.h>

// Problem constants
#define T_LEN 1200
#define BATCH 32
#define IDIM  512
#define HDIM  512
#define G4    2048            // 4*H
#define XPN   78643200        // T*B*4H
#define NCTA  128             // persistent recurrence grid
#define NTHR  256

typedef unsigned long long u64;

// Packed fp32x2 FMA (issue-slot saver in the GEMM)
__device__ __forceinline__ void fma2(u64& d, u64 a, u64 b) {
    asm("fma.rn.f32x2 %0, %1, %2, %0;" : "+l"(d) : "l"(a), "l"(b));
}
__device__ __forceinline__ float2 unp2(u64 v) {
    float2 r; asm("mov.b64 {%0, %1}, %2;" : "=f"(r.x), "=f"(r.y) : "l"(v));
    return r;
}
__device__ __forceinline__ u64 dup2(float v) {
    u64 r; asm("mov.b64 %0, {%1, %1};" : "=l"(r) : "f"(v));
    return r;
}

// Scratch (device globals — no runtime allocation allowed)
// x_proj layout: [dir][ (t*2048 + n) * 32 + b ]   (batch-minor, ORIGINAL b)
__device__ float g_xp[2][XPN];
__device__ float g_h[2][2][BATCH * HDIM];   // [parity][dir][pb*512 + j]  (PERMUTED b)
__device__ unsigned g_arrive;               // grid-barrier counter
__device__ int g_perm[BATCH];               // permuted -> original b (len desc)
__device__ int g_slen[BATCH];               // lens sorted descending

// ---------------------------------------------------------------------------
__global__ void zero_out_kernel(float4* __restrict__ o) {
    const int n4 = (T_LEN * BATCH * HDIM) / 4;
    for (int i = blockIdx.x * blockDim.x + threadIdx.x; i < n4;
         i += gridDim.x * blockDim.x)
        o[i] = make_float4(0.f, 0.f, 0.f, 0.f);
}

__global__ void zero_state_kernel() {
    int i = blockIdx.x * blockDim.x + threadIdx.x;
    if (i < 2 * 2 * BATCH * HDIM)
        (&g_h[0][0][0])[i] = 0.f;
    if (i == 0) g_arrive = 0u;
}

// Sort batches by descending length (selection sort, 32 elems, 1 thread).
__global__ void sort_lens_kernel(const int* __restrict__ lens) {
    if (threadIdx.x == 0 && blockIdx.x == 0) {
        int l[BATCH], p[BATCH];
        for (int i = 0; i < BATCH; i++) { l[i] = lens[i]; p[i] = i; }
        for (int i = 0; i < BATCH - 1; i++) {
            int m = i;
            for (int j = i + 1; j < BATCH; j++)
                if (l[j] > l[m]) m = j;
            int tl = l[i]; l[i] = l[m]; l[m] = tl;
            int tp = p[i]; p[i] = p[m]; p[m] = tp;
        }
        for (int i = 0; i < BATCH; i++) { g_perm[i] = p[i]; g_slen[i] = l[i]; }
    }
}

// ---------------------------------------------------------------------------
// Input projection GEMM (proven): M=38400, N=2048, K=512.
// Output b-minor: xp[(t*2048 + n)*32 + b]  (original b).
// ---------------------------------------------------------------------------
__global__ __launch_bounds__(256, 2)
void xproj_gemm(const float* __restrict__ x, const int* __restrict__ lens,
                const float* __restrict__ w, const float* __restrict__ b1,
                const float* __restrict__ b2, int rev)
{
    __shared__ float as[2][8][132];
    __shared__ float bs[2][8][132];
    float* __restrict__ out = g_xp[rev];

    const int tid = threadIdx.x;
    const int m0 = blockIdx.x * 128;
    const int n0 = blockIdx.y * 128;

    const int lr = tid >> 1;
    const int lk = (tid & 1) * 4;

    const int m = m0 + lr;
    const float* arow;
    if (!rev) {
        arow = x + (size_t)m * IDIM;
    } else {
        int t = m >> 5, b = m & 31;
        int st = lens[b] - 1 - t;
        if (st < 0) st = 0;
        arow = x + ((size_t)st * BATCH + b) * IDIM;
    }
    const float* brow = w + (size_t)(n0 + lr) * IDIM;

    float4 areg = *(const float4*)(arow + lk);
    float4 breg = *(const float4*)(brow + lk);

    u64 acc2[8][4];
#pragma unroll
    for (int i = 0; i < 8; i++)
#pragma unroll
        for (int p = 0; p < 4; p++) acc2[i][p] = 0ULL;

    const int wid = tid >> 5, lane = tid & 31;
    const int wm = (wid >> 1) * 32, wn = (wid & 1) * 64;
    const int lm = (lane & 3) * 4,  ln = (lane >> 2) * 4;

    as[0][lk + 0][lr] = areg.x; as[0][lk + 1][lr] = areg.y;
    as[0][lk + 2][lr] = areg.z; as[0][lk + 3][lr] = areg.w;
    bs[0][lk + 0][lr] = breg.x; bs[0][lk + 1][lr] = breg.y;
    bs[0][lk + 2][lr] = breg.z; bs[0][lk + 3][lr] = breg.w;
    __syncthreads();

    int buf = 0;
    for (int k0 = 8; k0 <= IDIM; k0 += 8) {
        const bool more = (k0 < IDIM);
        if (more) {
            areg = *(const float4*)(arow + k0 + lk);
            breg = *(const float4*)(brow + k0 + lk);
        }
#pragma unroll
        for (int kk = 0; kk < 8; kk++) {
            float4 a0  = *(const float4*)&as[buf][kk][wm + lm];
            float4 a1  = *(const float4*)&as[buf][kk][wm + lm + 16];
            ulonglong2 bq0 = *(const ulonglong2*)&bs[buf][kk][wn + ln];
            ulonglong2 bq1 = *(const ulonglong2*)&bs[buf][kk][wn + ln + 32];
            u64 b2v[4] = {bq0.x, bq0.y, bq1.x, bq1.y};
            float av[8] = {a0.x, a0.y, a0.z, a0.w, a1.x, a1.y, a1.z, a1.w};
#pragma unroll
            for (int i = 0; i < 8; i++) {
                u64 a2 = dup2(av[i]);
#pragma unroll
                for (int p = 0; p < 4; p++)
                    fma2(acc2[i][p], a2, b2v[p]);
            }
        }
        if (more) {
            buf ^= 1;
            as[buf][lk + 0][lr] = areg.x; as[buf][lk + 1][lr] = areg.y;
            as[buf][lk + 2][lr] = areg.z; as[buf][lk + 3][lr] = areg.w;
            bs[buf][lk + 0][lr] = breg.x; bs[buf][lk + 1][lr] = breg.y;
            bs[buf][lk + 2][lr] = breg.z; bs[buf][lk + 3][lr] = breg.w;
            __syncthreads();
        }
    }

    const int c0 = n0 + wn + ln;
    float bias[8];
#pragma unroll
    for (int p = 0; p < 4; p++) {
        int cc = c0 + (p & 1) * 2 + (p >> 1) * 32;
        bias[p * 2 + 0] = b1[cc + 0] + b2[cc + 0];
        bias[p * 2 + 1] = b1[cc + 1] + b2[cc + 1];
    }
#pragma unroll
    for (int i = 0; i < 8; i++) {
        int r = m0 + wm + lm + (i & 3) + ((i >= 4) ? 16 : 0);
        int t_ = r >> 5, b_ = r & 31;
        size_t base = ((size_t)t_ * G4) * 32 + b_;
#pragma unroll
        for (int p = 0; p < 4; p++) {
            int cc = c0 + (p & 1) * 2 + (p >> 1) * 32;
            float2 v = unp2(acc2[i][p]);
            out[base + (size_t)(cc + 0) * 32] = v.x + bias[p * 2 + 0];
            out[base + (size_t)(cc + 1) * 32] = v.y + bias[p * 2 + 1];
        }
    }
}

// ---------------------------------------------------------------------------
// Persistent recurrence (R5 structure + length-sorted batch-group skipping):
// 128 CTAs = 2 dir x 64 j-blocks (8 j each), 256 threads; intra-CTA K split
// across 8 warps; one grid barrier per step; cells register-resident.
// b-space PERMUTED by descending length; a thread's 8-batch group skips all
// hv loads + FMAs once its max length <= t.
// ---------------------------------------------------------------------------
#define SMEM_FLOATS (16384 + 16384 + 8192)
#define SMEM_BYTES  (SMEM_FLOATS * 4)

#define WSW(r, c) (((r) << 9) + ((((c) ^ (((r) >> 2) & 7)) << 2)))
#define HSW(b, c) (((b) << 9) + ((((c) ^ (((b) >> 3) & 3)) << 2)))

__global__ __launch_bounds__(NTHR)
void lstm_persist(const float* __restrict__ whh_f,
                  const float* __restrict__ whh_b,
                  float* __restrict__ out)
{
    extern __shared__ float sm[];
    float* ws  = sm;                  // [32 gate-rows][512] swizzled
    float* hs  = sm + 16384;          // [32 pb][512] swizzled
    float* red = sm + 32768;          // [8 ks][32 r][32 pb]

    __shared__ int sgl[4];            // per-8-batch-group max length

    const int bid = blockIdx.x;
    const int dir = bid >> 6;
    const int j0  = (bid & 63) << 3;
    const int tid = threadIdx.x;
    const int ks  = tid >> 5;
    const int ln  = tid & 31;

    const float* __restrict__ whh = dir ? whh_b : whh_f;

#pragma unroll
    for (int it = 0; it < 16; it++) {
        int cid = it * 256 + tid;
        int r = cid >> 7, c = cid & 127;
        int g = r >> 3, jl = r & 7;
        float4 v = *(const float4*)(whh +
            (size_t)(g * HDIM + j0 + jl) * HDIM + (c << 2));
        *(float4*)&ws[WSW(r, c)] = v;
    }
    if (tid < 4) sgl[tid] = g_slen[tid << 3];

    const int rg = ln >> 2;
    const int bg = ln & 3;            // this thread's 8-batch group (permuted)

    const int b_c   = tid & 31;       // permuted batch index of this cell
    const int j_c   = tid >> 5;
    const int ob_c  = g_perm[b_c];    // original batch
    const int len_c = g_slen[b_c];

    float c_reg = 0.f, h_reg = 0.f;

    const int l16 = ln >> 4;
    const int l15 = ln & 15;

    __syncthreads();

    const int glen_bg = sgl[bg];      // group active horizon (compute phase)

    for (int t = 0; t < T_LEN; t++) {
        // Prefetch xp for this cell (b-minor, original b) — only if active
        float xg0 = 0.f, xg1 = 0.f, xg2 = 0.f, xg3 = 0.f;
        if (t < len_c) {
            const float* xb =
                g_xp[dir] + ((size_t)t * G4 + j0 + j_c) * 32 + ob_c;
            xg0 = __ldg(xb + (size_t)0 * 512 * 32);
            xg1 = __ldg(xb + (size_t)1 * 512 * 32);
            xg2 = __ldg(xb + (size_t)2 * 512 * 32);
            xg3 = __ldg(xb + (size_t)3 * 512 * 32);
        }

        // h k-slice copy (permuted space); skip frozen 8-batch groups
        const float* __restrict__ hin = g_h[t & 1][dir];
#pragma unroll
        for (int i = 0; i < 16; i++) {
            int b = i * 2 + l16;
            if (t < sgl[b >> 3]) {
                int c = (ks << 4) + l15;
                float4 v = __ldcg((const float4*)(hin + (b << 9) + (c << 2)));
                *(float4*)&hs[HSW(b, c)] = v;
            }
        }
        __syncwarp();

        if (t < glen_bg) {
            float acc[4][8];
#pragma unroll
            for (int rr = 0; rr < 4; rr++)
#pragma unroll
                for (int i = 0; i < 8; i++) acc[rr][i] = 0.f;

            const int c0 = ks << 4;
#pragma unroll 2
            for (int c = c0; c < c0 + 16; c++) {
                float4 hv[8];
                const int hsw = ((c ^ bg) << 2);
#pragma unroll
                for (int i = 0; i < 8; i++)
                    hv[i] = *(const float4*)&hs[(((bg << 3) + i) << 9) + hsw];
                float4 wv[4];
                const int wsw = ((c ^ rg) << 2);
#pragma unroll
                for (int rr = 0; rr < 4; rr++)
                    wv[rr] = *(const float4*)&ws[(((rg << 2) + rr) << 9) + wsw];
#pragma unroll
                for (int rr = 0; rr < 4; rr++)
#pragma unroll
                    for (int i = 0; i < 8; i++)
                        acc[rr][i] += wv[rr].x * hv[i].x + wv[rr].y * hv[i].y +
                                      wv[rr].z * hv[i].z + wv[rr].w * hv[i].w;
            }

#pragma unroll
            for (int rr = 0; rr < 4; rr++) {
                int r = (rg << 2) + rr;
                float* dst = red + (ks << 10) + (r << 5) + (bg << 3);
                *(float4*)(dst + 0) = make_float4(acc[rr][0], acc[rr][1],
                                                  acc[rr][2], acc[rr][3]);
                *(float4*)(dst + 4) = make_float4(acc[rr][4], acc[rr][5],
                                                  acc[rr][6], acc[rr][7]);
            }
        }
        __syncthreads();

        if (t < len_c) {
            float s0 = xg0, s1 = xg1, s2 = xg2, s3 = xg3;
#pragma unroll
            for (int q = 0; q < 8; q++) {
                const float* pq = red + (q << 10) + b_c;
                s0 += pq[(0 * 8 + j_c) << 5];
                s1 += pq[(1 * 8 + j_c) << 5];
                s2 += pq[(2 * 8 + j_c) << 5];
                s3 += pq[(3 * 8 + j_c) << 5];
            }
            float gi = 1.f / (1.f + __expf(-s0));
            float gf = 1.f / (1.f + __expf(-s1));
            float gg = tanhf(s2);
            float go = 1.f / (1.f + __expf(-s3));
            c_reg = gf * c_reg + gi * gg;
            h_reg = go * tanhf(c_reg);
            const int to = dir ? (len_c - 1 - t) : t;
            atomicAdd(out + ((size_t)to * BATCH + ob_c) * HDIM + j0 + j_c,
                      h_reg);
        }
        // publish h (frozen value past length) to the other parity, permuted
        __stcg(g_h[(t + 1) & 1][dir] + (b_c << 9) + j0 + j_c, h_reg);

        // ---- single grid barrier per step ----
        __threadfence();
        __syncthreads();
        if (tid == 0) {
            atomicAdd(&g_arrive, 1u);
            const unsigned tgt = (unsigned)(t + 1) * NCTA;
            while (*(volatile unsigned*)&g_arrive < tgt) { }
            __threadfence();
        }
        __syncthreads();
    }

    // Final states (original b): h_n (2,B,H) then c_n (2,B,H)
    const size_t base = (size_t)T_LEN * BATCH * HDIM;
    out[base + dir * BATCH * HDIM + (ob_c << 9) + j0 + j_c] = h_reg;
    out[base + 2 * BATCH * HDIM + dir * BATCH * HDIM + (ob_c << 9) + j0 + j_c]
        = c_reg;
}

// ---------------------------------------------------------------------------
extern "C" void kernel_launch(void* const* d_in, const int* in_sizes, int n_in,
                              void* d_out, int out_size) {
    (void)in_sizes; (void)n_in; (void)out_size;
    const float* x      = (const float*)d_in[0];
    const int*   lens   = (const int*)d_in[1];
    const float* w_ih_f = (const float*)d_in[2];
    const float* w_hh_f = (const float*)d_in[3];
    const float* b_ih_f = (const float*)d_in[4];
    const float* b_hh_f = (const float*)d_in[5];
    const float* w_ih_b = (const float*)d_in[6];
    const float* w_hh_b = (const float*)d_in[7];
    const float* b_ih_b = (const float*)d_in[8];
    const float* b_hh_b = (const float*)d_in[9];
    float* out = (float*)d_out;

    cudaFuncSetAttribute(lstm_persist,
                         cudaFuncAttributeMaxDynamicSharedMemorySize, SMEM_BYTES);

    zero_out_kernel<<<2048, 256>>>((float4*)out);
    zero_state_kernel<<<256, 256>>>();
    sort_lens_kernel<<<1, 32>>>(lens);

    dim3 gg(300, 16);  // M/128 x N/128
    xproj_gemm<<<gg, 256>>>(x, lens, w_ih_f, b_ih_f, b_hh_f, 0);
    xproj_gemm<<<gg, 256>>>(x, lens, w_ih_b, b_ih_b, b_hh_b, 1);

    lstm_persist<<<NCTA, NTHR, SMEM_BYTES>>>(w_hh_f, w_hh_b, out);
}

// round 16
// speedup vs baseline: 1.1069x; 1.0890x over previous
#include <cuda_runtime.h>
#include <stdint.h>
#include <math.h>

// Problem constants
#define T_LEN 1200
#define BATCH 32
#define IDIM  512
#define HDIM  512
#define G4    2048            // 4*H
#define XPN   78643200        // T*B*4H
#define NCTA  128             // persistent recurrence grid
#define NTHR  256

typedef unsigned long long u64;

// Packed fp32x2 FMA (issue-slot saver in the GEMM)
__device__ __forceinline__ void fma2(u64& d, u64 a, u64 b) {
    asm("fma.rn.f32x2 %0, %1, %2, %0;" : "+l"(d) : "l"(a), "l"(b));
}
__device__ __forceinline__ float2 unp2(u64 v) {
    float2 r; asm("mov.b64 {%0, %1}, %2;" : "=f"(r.x), "=f"(r.y) : "l"(v));
    return r;
}
__device__ __forceinline__ u64 dup2(float v) {
    u64 r; asm("mov.b64 %0, {%1, %1};" : "=l"(r) : "f"(v));
    return r;
}

// Scratch (device globals — no runtime allocation allowed)
// x_proj layout: [dir][ (t*2048 + n) * 32 + pb ]   (PERMUTED-batch minor)
__device__ float g_xp[2][XPN];
// h layout: [parity][dir][ quad(8) ][ j(512) ][ bb(4) ]  (quad = pb>>2)
__device__ float g_h[2][2][BATCH * HDIM];
__device__ unsigned g_arrive;               // grid-barrier counter
__device__ int g_perm[BATCH];               // permuted -> original b (len desc)
__device__ int g_iperm[BATCH];              // original -> permuted
__device__ int g_slen[BATCH];               // lens sorted descending

// ---------------------------------------------------------------------------
__global__ void zero_out_kernel(float4* __restrict__ o) {
    const int n4 = (T_LEN * BATCH * HDIM) / 4;
    for (int i = blockIdx.x * blockDim.x + threadIdx.x; i < n4;
         i += gridDim.x * blockDim.x)
        o[i] = make_float4(0.f, 0.f, 0.f, 0.f);
}

__global__ void zero_state_kernel() {
    int i = blockIdx.x * blockDim.x + threadIdx.x;
    if (i < 2 * 2 * BATCH * HDIM)
        (&g_h[0][0][0])[i] = 0.f;
    if (i == 0) g_arrive = 0u;
}

// Sort batches by descending length (selection sort, 32 elems, 1 thread).
__global__ void sort_lens_kernel(const int* __restrict__ lens) {
    if (threadIdx.x == 0 && blockIdx.x == 0) {
        int l[BATCH], p[BATCH];
        for (int i = 0; i < BATCH; i++) { l[i] = lens[i]; p[i] = i; }
        for (int i = 0; i < BATCH - 1; i++) {
            int m = i;
            for (int j = i + 1; j < BATCH; j++)
                if (l[j] > l[m]) m = j;
            int tl = l[i]; l[i] = l[m]; l[m] = tl;
            int tp = p[i]; p[i] = p[m]; p[m] = tp;
        }
        for (int i = 0; i < BATCH; i++) {
            g_perm[i] = p[i];
            g_iperm[p[i]] = i;
            g_slen[i] = l[i];
        }
    }
}

// ---------------------------------------------------------------------------
// Input projection GEMM (proven): M=38400, N=2048, K=512.
// Output b-minor with PERMUTED columns: xp[(t*2048 + n)*32 + iperm[b]].
// ---------------------------------------------------------------------------
__global__ __launch_bounds__(256, 2)
void xproj_gemm(const float* __restrict__ x, const int* __restrict__ lens,
                const float* __restrict__ w, const float* __restrict__ b1,
                const float* __restrict__ b2, int rev)
{
    __shared__ float as[2][8][132];
    __shared__ float bs[2][8][132];
    float* __restrict__ out = g_xp[rev];

    const int tid = threadIdx.x;
    const int m0 = blockIdx.x * 128;
    const int n0 = blockIdx.y * 128;

    const int lr = tid >> 1;
    const int lk = (tid & 1) * 4;

    const int m = m0 + lr;
    const float* arow;
    if (!rev) {
        arow = x + (size_t)m * IDIM;
    } else {
        int t = m >> 5, b = m & 31;
        int st = lens[b] - 1 - t;
        if (st < 0) st = 0;
        arow = x + ((size_t)st * BATCH + b) * IDIM;
    }
    const float* brow = w + (size_t)(n0 + lr) * IDIM;

    float4 areg = *(const float4*)(arow + lk);
    float4 breg = *(const float4*)(brow + lk);

    u64 acc2[8][4];
#pragma unroll
    for (int i = 0; i < 8; i++)
#pragma unroll
        for (int p = 0; p < 4; p++) acc2[i][p] = 0ULL;

    const int wid = tid >> 5, lane = tid & 31;
    const int wm = (wid >> 1) * 32, wn = (wid & 1) * 64;
    const int lm = (lane & 3) * 4,  ln = (lane >> 2) * 4;

    as[0][lk + 0][lr] = areg.x; as[0][lk + 1][lr] = areg.y;
    as[0][lk + 2][lr] = areg.z; as[0][lk + 3][lr] = areg.w;
    bs[0][lk + 0][lr] = breg.x; bs[0][lk + 1][lr] = breg.y;
    bs[0][lk + 2][lr] = breg.z; bs[0][lk + 3][lr] = breg.w;
    __syncthreads();

    int buf = 0;
    for (int k0 = 8; k0 <= IDIM; k0 += 8) {
        const bool more = (k0 < IDIM);
        if (more) {
            areg = *(const float4*)(arow + k0 + lk);
            breg = *(const float4*)(brow + k0 + lk);
        }
#pragma unroll
        for (int kk = 0; kk < 8; kk++) {
            float4 a0  = *(const float4*)&as[buf][kk][wm + lm];
            float4 a1  = *(const float4*)&as[buf][kk][wm + lm + 16];
            ulonglong2 bq0 = *(const ulonglong2*)&bs[buf][kk][wn + ln];
            ulonglong2 bq1 = *(const ulonglong2*)&bs[buf][kk][wn + ln + 32];
            u64 b2v[4] = {bq0.x, bq0.y, bq1.x, bq1.y};
            float av[8] = {a0.x, a0.y, a0.z, a0.w, a1.x, a1.y, a1.z, a1.w};
#pragma unroll
            for (int i = 0; i < 8; i++) {
                u64 a2 = dup2(av[i]);
#pragma unroll
                for (int p = 0; p < 4; p++)
                    fma2(acc2[i][p], a2, b2v[p]);
            }
        }
        if (more) {
            buf ^= 1;
            as[buf][lk + 0][lr] = areg.x; as[buf][lk + 1][lr] = areg.y;
            as[buf][lk + 2][lr] = areg.z; as[buf][lk + 3][lr] = areg.w;
            bs[buf][lk + 0][lr] = breg.x; bs[buf][lk + 1][lr] = breg.y;
            bs[buf][lk + 2][lr] = breg.z; bs[buf][lk + 3][lr] = breg.w;
            __syncthreads();
        }
    }

    const int c0 = n0 + wn + ln;
    float bias[8];
#pragma unroll
    for (int p = 0; p < 4; p++) {
        int cc = c0 + (p & 1) * 2 + (p >> 1) * 32;
        bias[p * 2 + 0] = b1[cc + 0] + b2[cc + 0];
        bias[p * 2 + 1] = b1[cc + 1] + b2[cc + 1];
    }
#pragma unroll
    for (int i = 0; i < 8; i++) {
        int r = m0 + wm + lm + (i & 3) + ((i >= 4) ? 16 : 0);
        int t_ = r >> 5, b_ = r & 31;
        int pb_ = g_iperm[b_];
        size_t base = ((size_t)t_ * G4) * 32 + pb_;
#pragma unroll
        for (int p = 0; p < 4; p++) {
            int cc = c0 + (p & 1) * 2 + (p >> 1) * 32;
            float2 v = unp2(acc2[i][p]);
            out[base + (size_t)(cc + 0) * 32] = v.x + bias[p * 2 + 0];
            out[base + (size_t)(cc + 1) * 32] = v.y + bias[p * 2 + 1];
        }
    }
}

// ---------------------------------------------------------------------------
// Persistent recurrence, warp-level batch skip:
// 128 CTAs = 2 dir x 64 j-blocks (8 j each), 256 threads.
// Warp w owns permuted-batch quad 4w..4w+3; lane r owns gate-row r and
// accumulates the FULL k=512 dot (no k-split reduction). Skip is per-warp:
// warp w idles once t >= slen[4w]. One grid barrier per step.
// SMEM: ws 64KB (W swizzled) + hs 64KB (warp-private h) + red 4.6KB.
// ---------------------------------------------------------------------------
#define RED_PITCH 36
#define SMEM_FLOATS (16384 + 16384 + 32 * RED_PITCH)
#define SMEM_BYTES  (SMEM_FLOATS * 4)       // 135,680 -> 1 CTA/SM

__global__ __launch_bounds__(NTHR)
void lstm_persist(const float* __restrict__ whh_f,
                  const float* __restrict__ whh_b,
                  float* __restrict__ out)
{
    extern __shared__ float sm[];
    float* ws  = sm;                  // [32 gate-rows][512] XOR-swizzled
    float* hs  = sm + 16384;          // [8 warps][512 k][4 bb]  (warp-private)
    float* red = sm + 32768;          // [32 r][RED_PITCH]

    const int bid = blockIdx.x;
    const int dir = bid >> 6;
    const int j0  = (bid & 63) << 3;
    const int tid = threadIdx.x;
    const int w   = tid >> 5;         // warp: batch quad AND (cell) jl
    const int r   = tid & 31;         // lane: gate-row AND (cell) pb

    const float* __restrict__ whh = dir ? whh_b : whh_f;

    // ---- load W slice once: ws row rr = g*8+jl <-> whh row g*512+j0+jl ----
#pragma unroll
    for (int it = 0; it < 16; it++) {
        int cid = it * 256 + tid;          // 0..4095 float4 chunks
        int rr = cid >> 7, c = cid & 127;
        int g = rr >> 3, jl = rr & 7;
        float4 v = *(const float4*)(whh +
            (size_t)(g * HDIM + j0 + jl) * HDIM + (c << 2));
        *(float4*)&ws[(rr << 9) + (((c ^ (rr & 7)) << 2))] = v;
    }

    const int sglw  = g_slen[w << 2];     // warp's active horizon
    const int len_c = g_slen[r];          // cell batch length (pb = r)
    const int ob_c  = g_perm[r];          // original batch of this cell

    float c_reg = 0.f, h_reg = 0.f;

    float* hsw = hs + (w << 11);          // this warp's 2048-float h buffer
    const float* wr = ws + (r << 9);
    const int key = r & 7;

    __syncthreads();  // ws ready

    for (int t = 0; t < T_LEN; t++) {
        // xp prefetch for this thread's cell (jl=w, pb=r) — coalesced in r
        float xg0 = 0.f, xg1 = 0.f, xg2 = 0.f, xg3 = 0.f;
        if (t < len_c) {
            const float* xb = g_xp[dir] + ((size_t)t * G4 + j0 + w) * 32 + r;
            xg0 = __ldg(xb + (size_t)0 * 512 * 32);
            xg1 = __ldg(xb + (size_t)1 * 512 * 32);
            xg2 = __ldg(xb + (size_t)2 * 512 * 32);
            xg3 = __ldg(xb + (size_t)3 * 512 * 32);
        }

        if (t < sglw) {
            // ---- h copy: this warp's quad, 8KB contiguous, coalesced ----
            const float* hb = g_h[t & 1][dir] + (w << 11);
#pragma unroll
            for (int i = 0; i < 16; i++) {
                float4 v = __ldcg((const float4*)(hb + i * 128 + (r << 2)));
                *(float4*)(hsw + i * 128 + (r << 2)) = v;
            }
            __syncwarp();

            // ---- full-k dot: lane r = gate-row, 4 batches ----
            float a0 = 0.f, a1 = 0.f, a2 = 0.f, a3 = 0.f;
#pragma unroll 4
            for (int c = 0; c < 128; c++) {
                float4 wv = *(const float4*)(wr + ((c ^ key) << 2));
                float4 h0 = *(const float4*)(hsw + (c << 4) + 0);
                float4 h1 = *(const float4*)(hsw + (c << 4) + 4);
                float4 h2 = *(const float4*)(hsw + (c << 4) + 8);
                float4 h3 = *(const float4*)(hsw + (c << 4) + 12);
                a0 += wv.x * h0.x + wv.y * h1.x + wv.z * h2.x + wv.w * h3.x;
                a1 += wv.x * h0.y + wv.y * h1.y + wv.z * h2.y + wv.w * h3.y;
                a2 += wv.x * h0.z + wv.y * h1.z + wv.z * h2.z + wv.w * h3.z;
                a3 += wv.x * h0.w + wv.y * h1.w + wv.z * h2.w + wv.w * h3.w;
            }
            *(float4*)&red[r * RED_PITCH + (w << 2)] =
                make_float4(a0, a1, a2, a3);
        }
        __syncthreads();

        // ---- LSTM cell: thread (jl=w, pb=r) ----
        if (t < len_c) {
            float s0 = xg0 + red[(0 * 8 + w) * RED_PITCH + r];
            float s1 = xg1 + red[(1 * 8 + w) * RED_PITCH + r];
            float s2 = xg2 + red[(2 * 8 + w) * RED_PITCH + r];
            float s3 = xg3 + red[(3 * 8 + w) * RED_PITCH + r];
            float gi = 1.f / (1.f + __expf(-s0));
            float gf = 1.f / (1.f + __expf(-s1));
            float gg = tanhf(s2);
            float go = 1.f / (1.f + __expf(-s3));
            c_reg = gf * c_reg + gi * gg;
            h_reg = go * tanhf(c_reg);
            const int to = dir ? (len_c - 1 - t) : t;
            atomicAdd(out + ((size_t)to * BATCH + ob_c) * HDIM + j0 + w,
                      h_reg);
        }
        // publish h (frozen value past length) to the other parity:
        // layout [quad][j][bb]
        __stcg(&g_h[(t + 1) & 1][dir]
                   [((r >> 2) << 11) + ((j0 + w) << 2) + (r & 3)], h_reg);

        // ---- single grid barrier per step ----
        __threadfence();
        __syncthreads();
        if (tid == 0) {
            atomicAdd(&g_arrive, 1u);
            const unsigned tgt = (unsigned)(t + 1) * NCTA;
            while (*(volatile unsigned*)&g_arrive < tgt) { }
            __threadfence();
        }
        __syncthreads();
    }

    // Final states (original b): h_n (2,B,H) then c_n (2,B,H)
    const size_t base = (size_t)T_LEN * BATCH * HDIM;
    out[base + dir * BATCH * HDIM + (ob_c << 9) + j0 + w] = h_reg;
    out[base + 2 * BATCH * HDIM + dir * BATCH * HDIM + (ob_c << 9) + j0 + w]
        = c_reg;
}

// ---------------------------------------------------------------------------
extern "C" void kernel_launch(void* const* d_in, const int* in_sizes, int n_in,
                              void* d_out, int out_size) {
    (void)in_sizes; (void)n_in; (void)out_size;
    const float* x      = (const float*)d_in[0];
    const int*   lens   = (const int*)d_in[1];
    const float* w_ih_f = (const float*)d_in[2];
    const float* w_hh_f = (const float*)d_in[3];
    const float* b_ih_f = (const float*)d_in[4];
    const float* b_hh_f = (const float*)d_in[5];
    const float* w_ih_b = (const float*)d_in[6];
    const float* w_hh_b = (const float*)d_in[7];
    const float* b_ih_b = (const float*)d_in[8];
    const float* b_hh_b = (const float*)d_in[9];
    float* out = (float*)d_out;

    cudaFuncSetAttribute(lstm_persist,
                         cudaFuncAttributeMaxDynamicSharedMemorySize, SMEM_BYTES);

    zero_out_kernel<<<2048, 256>>>((float4*)out);
    zero_state_kernel<<<256, 256>>>();
    sort_lens_kernel<<<1, 32>>>(lens);

    dim3 gg(300, 16);  // M/128 x N/128
    xproj_gemm<<<gg, 256>>>(x, lens, w_ih_f, b_ih_f, b_hh_f, 0);
    xproj_gemm<<<gg, 256>>>(x, lens, w_ih_b, b_ih_b, b_hh_b, 1);

    lstm_persist<<<NCTA, NTHR, SMEM_BYTES>>>(w_hh_f, w_hh_b, out);
}